// round 14
// baseline (speedup 1.0000x reference)
#include <cuda_runtime.h>
#include <cuda_fp16.h>
#include <float.h>
#include <math.h>
#include <stdint.h>

#define NB 8
#define NP 2048
#define ND 512
#define NK 16
#define NCAND 32

// ---------------- device scratch (no allocations allowed) -------------------
__device__ __half g_fqh[(size_t)NB * NP * ND];        // normalized ffq, fp16
__device__ __half g_fph[(size_t)NB * NP * ND];        // normalized ffp, fp16
__device__ float  g_nq[NB * NP];                      // 1/(||ffq||+eps)
__device__ float  g_np[NB * NP];                      // 1/(||ffp||+eps)
__device__ __half g_w1h[(size_t)NB * NP * NP];        // similarity, fp16
__device__ int    g_sel[NB * NP * NK];                // final top-16 (global idx)

// ---------------- helpers ---------------------------------------------------
__device__ __forceinline__ uint32_t smem_u32(const void* p) {
    uint32_t a;
    asm("{ .reg .u64 t; cvta.to.shared.u64 t, %1; cvt.u32.u64 %0, t; }" : "=r"(a) : "l"(p));
    return a;
}
#define SWZ(off) ((off) ^ (((off) >> 3) & 0x70))

__device__ __forceinline__ void cp16(uint32_t dst, const void* src) {
    asm volatile("cp.async.cg.shared.global [%0], [%1], 16;" :: "r"(dst), "l"(src));
}
#define CP_COMMIT() asm volatile("cp.async.commit_group;" ::: "memory")
#define CP_WAIT(n)  asm volatile("cp.async.wait_group %0;" :: "n"(n) : "memory")

#define LDSM4(r, addr)                                                          \
    asm volatile("ldmatrix.sync.aligned.m8n8.x4.shared.b16 {%0,%1,%2,%3}, [%4];" \
        : "=r"((r)[0]), "=r"((r)[1]), "=r"((r)[2]), "=r"((r)[3]) : "r"(addr))

__device__ __forceinline__ void mma16816(float* d, const uint32_t* a,
                                         uint32_t b0, uint32_t b1) {
    asm volatile(
        "mma.sync.aligned.m16n8k16.row.col.f32.f16.f16.f32 "
        "{%0,%1,%2,%3},{%4,%5,%6,%7},{%8,%9},{%0,%1,%2,%3};"
        : "+f"(d[0]), "+f"(d[1]), "+f"(d[2]), "+f"(d[3])
        : "r"(a[0]), "r"(a[1]), "r"(a[2]), "r"(a[3]), "r"(b0), "r"(b1));
}

// ---------------------------------------------------------------------------
// Normalize rows by (L2 + 1e-8) for both tensors in one launch (blockIdx.y
// selects ffp/ffq). Norm reduction = exact validated R1 arithmetic.
// ---------------------------------------------------------------------------
__global__ void k_normalize2(const float* __restrict__ srcp, __half* __restrict__ dstp,
                             float* __restrict__ invnp,
                             const float* __restrict__ srcq, __half* __restrict__ dstq,
                             float* __restrict__ invnq) {
    const float* src = blockIdx.y ? srcq : srcp;
    __half* dst = blockIdx.y ? dstq : dstp;
    float* invn = blockIdx.y ? invnq : invnp;
    int row  = blockIdx.x * 8 + (threadIdx.x >> 5);
    int lane = threadIdx.x & 31;
    const float* s = src + (size_t)row * ND;
    float ss = 0.f;
    for (int d = lane; d < ND; d += 32) { float v = s[d]; ss = fmaf(v, v, ss); }
#pragma unroll
    for (int o = 16; o; o >>= 1) ss += __shfl_xor_sync(0xffffffffu, ss, o);
    float inv = 1.0f / (sqrtf(ss) + 1e-8f);
    if (lane == 0) invn[row] = inv;
    const float2* s2 = (const float2*)s;
    __half2* d2 = (__half2*)(dst + (size_t)row * ND);
#pragma unroll
    for (int i = 0; i < 8; i++) {
        float2 v = s2[lane + 32 * i];
        d2[lane + 32 * i] = __floats2half2_rn(v.x * inv, v.y * inv);
    }
}

// ---------------------------------------------------------------------------
// HMMA fp16 GEMM: w1[b] = fq[b] @ fp[b]^T -> fp16.
// 128x128 tile, BK=64, cp.async double buffer, 8 warps in 4(M) x 2(N),
// warp tile 32x64, mma.m16n8k16, fp32 accumulate.
// ---------------------------------------------------------------------------
#define BM 128
#define BN 128
#define BK 64

__global__ __launch_bounds__(256) void k_gemm_hmma() {
    extern __shared__ char sm[];
    const uint32_t sb = smem_u32(sm);
    const int tid = threadIdx.x, lane = tid & 31, wid = tid >> 5;
    const int wm = wid & 3, wn = wid >> 2;
    const int bz = blockIdx.z;
    const __half* Ag = g_fqh + ((size_t)bz * NP + blockIdx.y * BM) * ND;
    const __half* Bg = g_fph + ((size_t)bz * NP + blockIdx.x * BN) * ND;

    auto load = [&](int kc, int buf) {
        uint32_t abase = sb + buf * 32768;
        const __half* ap = Ag + kc * BK;
#pragma unroll
        for (int i = 0; i < 4; i++) {
            int id = tid + i * 256;
            int r = id >> 3, c = id & 7;
            cp16(abase + SWZ(r * 128 + c * 16), ap + (size_t)r * ND + c * 8);
        }
        uint32_t bbase = abase + 16384;
        const __half* bp = Bg + kc * BK;
#pragma unroll
        for (int i = 0; i < 4; i++) {
            int id = tid + i * 256;
            int r = id >> 3, c = id & 7;
            cp16(bbase + SWZ(r * 128 + c * 16), bp + (size_t)r * ND + c * 8);
        }
    };

    float acc[2][8][4];
#pragma unroll
    for (int t = 0; t < 2; t++)
#pragma unroll
        for (int n = 0; n < 8; n++)
#pragma unroll
            for (int i = 0; i < 4; i++) acc[t][n][i] = 0.f;

    load(0, 0);
    CP_COMMIT();

    const int lrow = lane & 15;
    const int lk16 = (lane >> 4) * 16;

#pragma unroll 1
    for (int c = 0; c < 8; c++) {
        int buf = c & 1;
        if (c < 7) { load(c + 1, buf ^ 1); CP_COMMIT(); CP_WAIT(1); }
        else       { CP_WAIT(0); }
        __syncthreads();
        uint32_t Asb = sb + buf * 32768;
        uint32_t Bsb = Asb + 16384;
#pragma unroll
        for (int ks = 0; ks < 4; ks++) {
            uint32_t a[2][4];
#pragma unroll
            for (int t = 0; t < 2; t++) {
                int row = wm * 32 + t * 16 + lrow;
                uint32_t off = (uint32_t)(row * 128 + ks * 32 + lk16) ^ ((row & 7) << 4);
                LDSM4(a[t], Asb + off);
            }
            uint32_t bfr[4][4];
#pragma unroll
            for (int j = 0; j < 4; j++) {
                int row = wn * 64 + j * 16 + lrow;
                uint32_t off = (uint32_t)(row * 128 + ks * 32 + lk16) ^ ((row & 7) << 4);
                LDSM4(bfr[j], Bsb + off);
            }
#pragma unroll
            for (int t = 0; t < 2; t++)
#pragma unroll
                for (int n8 = 0; n8 < 8; n8++) {
                    int j = n8 >> 1, hi = n8 & 1;
                    mma16816(acc[t][n8], a[t], bfr[j][hi ? 1 : 0], bfr[j][hi ? 3 : 2]);
                }
        }
        __syncthreads();
    }

    const int q0 = blockIdx.y * BM, p0 = blockIdx.x * BN;
#pragma unroll
    for (int t = 0; t < 2; t++)
#pragma unroll
        for (int n8 = 0; n8 < 8; n8++) {
            int m = q0 + wm * 32 + t * 16 + (lane >> 2);
            int n = p0 + wn * 64 + n8 * 8 + (lane & 3) * 2;
            size_t base = ((size_t)bz * NP + m) * NP + n;
            *(__half2*)(g_w1h + base) =
                __floats2half2_rn(acc[t][n8][0], acc[t][n8][1]);
            *(__half2*)(g_w1h + base + (size_t)8 * NP) =
                __floats2half2_rn(acc[t][n8][2], acc[t][n8][3]);
        }
}

// ---------------------------------------------------------------------------
// MERGED select: per-point top-32 candidates from fp16 w1 (identical buffered
// argmax algorithm) -> exact cp.async-staged rescore + bitonic sort.
// One WARP per point, 4 warps (128 threads) per block, 32.5 KB smem.
// Candidate list passes through per-warp smem instead of g_cand; both phases'
// arithmetic is bit-identical to the validated split kernels.
// ---------------------------------------------------------------------------
__global__ __launch_bounds__(128) void k_select(
    const float* __restrict__ ffp, const float* __restrict__ ffq,
    float* __restrict__ out)
{
    __shared__ __align__(16) float stile[4][2][32 * 32];   // 4 warps x 2 bufs x 4KB
    __shared__ int scand[4][NCAND];
    const int wid = threadIdx.x >> 5, lane = threadIdx.x & 31;
    const int pt = blockIdx.x * 4 + wid;
    const int b = pt >> 11;

    // ===== phase 1: top-32 candidate selection from fp16 w1 =====
    {
        const unsigned int* rp = ((const unsigned int*)g_w1h) + (size_t)pt * (NP / 2);
        unsigned int rv[32];
#pragma unroll
        for (int i = 0; i < 32; i++) rv[i] = rp[i * 32 + lane];

        float bv0 = -FLT_MAX, bv1 = -FLT_MAX, bv2 = -FLT_MAX, bv3 = -FLT_MAX;
        int   bi0 = 1 << 30,  bi1 = 1 << 30,  bi2 = 1 << 30,  bi3 = 1 << 30;

        auto ins = [&](float v, int id) {
            if (v > bv3) {
                if (v > bv1) {
                    if (v > bv0) {
                        bv3 = bv2; bi3 = bi2; bv2 = bv1; bi2 = bi1;
                        bv1 = bv0; bi1 = bi0; bv0 = v;  bi0 = id;
                    } else {
                        bv3 = bv2; bi3 = bi2; bv2 = bv1; bi2 = bi1;
                        bv1 = v;  bi1 = id;
                    }
                } else {
                    if (v > bv2) { bv3 = bv2; bi3 = bi2; bv2 = v; bi2 = id; }
                    else         { bv3 = v;  bi3 = id; }
                }
            }
        };
        auto build = [&]() {
            bv0 = bv1 = bv2 = bv3 = -FLT_MAX;
            bi0 = bi1 = bi2 = bi3 = 1 << 30;
#pragma unroll
            for (int i = 0; i < 32; i++) {
                float2 f = __half22float2(*(__half2*)&rv[i]);
                int base = (i * 32 + lane) << 1;
                ins(f.x, base);
                ins(f.y, base + 1);
            }
        };
        build();

#pragma unroll 1
        for (int it = 0; it < NCAND; it++) {
            float wv = bv0; int wi = bi0;
#pragma unroll
            for (int o = 16; o; o >>= 1) {
                float ov = __shfl_xor_sync(0xffffffffu, wv, o);
                int   oi = __shfl_xor_sync(0xffffffffu, wi, o);
                if (ov > wv || (ov == wv && oi < wi)) { wv = ov; wi = oi; }
            }
            if (lane == 0) scand[wid][it] = wi;
            if (bi0 == wi) {
                int slot = wi >> 6;
                __half2 h = *(__half2*)&rv[slot];
                if (wi & 1) h.y = __ushort_as_half((unsigned short)0xFC00);
                else        h.x = __ushort_as_half((unsigned short)0xFC00);
                rv[slot] = *(unsigned int*)&h;
                bv0 = bv1; bi0 = bi1; bv1 = bv2; bi1 = bi2;
                bv2 = bv3; bi2 = bi3; bv3 = -FLT_MAX; bi3 = 1 << 30;
                if (bv0 == -FLT_MAX) build();
            }
        }
    }
    __syncwarp();

    // ===== phase 2: exact rescore (bit-identical chain) + sort =====
    const float* fqr = ffq + (size_t)pt * ND;
    const float invq = g_nq[pt];
    float rqv[16];
#pragma unroll
    for (int i = 0; i < 16; i++) rqv[i] = fqr[i * 32 + lane] * invq;

    const int ci = scand[wid][lane];
    const float invp = g_np[b * NP + ci];
    const float* fpb = ffp + (size_t)b * NP * ND;

    const int part = lane & 7;
    const int rbase = lane >> 3;
    const uint32_t tb0 = smem_u32(stile[wid][0]);
    const uint32_t tb1 = smem_u32(stile[wid][1]);
    const int lsw = lane & 7;

    auto stage = [&](int ch, int buf) {
        uint32_t tb = buf ? tb1 : tb0;
#pragma unroll
        for (int i = 0; i < 8; i++) {
            int r = i * 4 + rbase;
            int cir = __shfl_sync(0xffffffffu, ci, r);
            const float* src = fpb + (size_t)cir * ND + ch * 32 + part * 4;
            uint32_t dst = tb + (uint32_t)(r * 128 + ((part ^ (r & 7)) << 4));
            cp16(dst, src);
        }
    };

    stage(0, 0);
    CP_COMMIT();

    float acc = 0.f;
#pragma unroll
    for (int ch = 0; ch < 16; ch++) {
        const int buf = ch & 1;
        if (ch < 15) { stage(ch + 1, buf ^ 1); CP_COMMIT(); CP_WAIT(1); }
        else         { CP_WAIT(0); }
        __syncwarp();
        const float* tb = (const float*)(buf ? stile[wid][1] : stile[wid][0]) + lane * 32;
#pragma unroll
        for (int j = 0; j < 8; j++) {
            float4 v = *(const float4*)(tb + ((j ^ lsw) << 2));
            float s0 = __shfl_sync(0xffffffffu, rqv[ch], j * 4 + 0);
            float s1 = __shfl_sync(0xffffffffu, rqv[ch], j * 4 + 1);
            float s2 = __shfl_sync(0xffffffffu, rqv[ch], j * 4 + 2);
            float s3 = __shfl_sync(0xffffffffu, rqv[ch], j * 4 + 3);
            acc = fmaf(v.x * invp, s0, acc);     // strictly sequential, fused
            acc = fmaf(v.y * invp, s1, acc);
            acc = fmaf(v.z * invp, s2, acc);
            acc = fmaf(v.w * invp, s3, acc);
        }
        __syncwarp();
    }

    unsigned int u = __float_as_uint(acc);
    unsigned int ou = (u & 0x80000000u) ? ~u : (u | 0x80000000u);
    unsigned long long key =
        ((unsigned long long)(~ou) << 32) | (unsigned)((ci << 5) | lane);
#pragma unroll
    for (int k = 2; k <= 32; k <<= 1) {
#pragma unroll
        for (int j = k >> 1; j > 0; j >>= 1) {
            unsigned long long o = __shfl_xor_sync(0xffffffffu, key, j);
            bool dirUp = ((lane & k) == 0);
            bool lower = ((lane & j) == 0);
            unsigned long long mn = (key < o) ? key : o;
            unsigned long long mx = (key < o) ? o : key;
            key = (lower == dirUp) ? mn : mx;
        }
    }
    if (lane < NK) {
        int idx = (int)((key >> 5) & 2047u);
        g_sel[pt * NK + lane] = idx;
        out[3 * NB * NP * 3 + pt * NK + lane] = (float)idx;
    }
}

// ---------------------------------------------------------------------------
// 3x3 inverse (adjugate) applied to a vector.
// ---------------------------------------------------------------------------
__device__ __forceinline__ void inv3_apply(const float* __restrict__ M,
                                           const float* __restrict__ v,
                                           float* __restrict__ o) {
    float a = M[0], b = M[1], c = M[2];
    float d = M[3], e = M[4], f = M[5];
    float g = M[6], h = M[7], i = M[8];
    float A  = e * i - f * h;
    float Bc = -(d * i - f * g);
    float Cc = d * h - e * g;
    float det = a * A + b * Bc + c * Cc;
    float id = 1.0f / det;
    float i00 = A * id,  i01 = -(b * i - c * h) * id, i02 = (b * f - c * e) * id;
    float i10 = Bc * id, i11 = (a * i - c * g) * id,  i12 = -(a * f - c * d) * id;
    float i20 = Cc * id, i21 = -(a * h - b * g) * id, i22 = (a * e - b * d) * id;
    o[0] = i00 * v[0] + i01 * v[1] + i02 * v[2];
    o[1] = i10 * v[0] + i11 * v[1] + i12 * v[2];
    o[2] = i20 * v[0] + i21 * v[1] + i22 * v[2];
}

// ---------------------------------------------------------------------------
// Pool (avg/max over the 16 winners) + refine linear + rotate-back + mask +
// add q. One block per point; float2 loads: each thread owns 2 adjacent
// channels (per-channel math identical; only thread->channel mapping changes,
// which perturbs the pv butterfly at ~1e-7, far under the 1e-3 tolerance).
// ---------------------------------------------------------------------------
__global__ __launch_bounds__(256) void k_pool(
    const float* __restrict__ ffp, const float* __restrict__ ffq,
    const float* __restrict__ R1,  const float* __restrict__ R2,
    const int*   __restrict__ cen, const float* __restrict__ W,
    const float* __restrict__ bvec, const float* __restrict__ q,
    float* __restrict__ out)
{
    __shared__ int   ssel[NK];
    __shared__ float wred[24];
    const int pt = blockIdx.x, b = pt >> 11;
    const int tid = threadIdx.x, lane = tid & 31, wid = tid >> 5;

    if (tid < NK) ssel[tid] = g_sel[pt * NK + tid];
    __syncthreads();

    const float* fpb = ffp + (size_t)b * NP * ND;
    const float2* fqr2 = (const float2*)(ffq + (size_t)pt * ND);
    const float2* W2 = (const float2*)W;

    float2 s = make_float2(0.f, 0.f);
    float2 mx = make_float2(-FLT_MAX, -FLT_MAX);
#pragma unroll
    for (int k = 0; k < NK; k++) {
        float2 v = __ldg((const float2*)(fpb + (size_t)ssel[k] * ND) + tid);
        s.x += v.x; s.y += v.y;
        mx.x = fmaxf(mx.x, v.x); mx.y = fmaxf(mx.y, v.y);
    }
    float2 avg = make_float2(s.x * (1.0f / 16.0f), s.y * (1.0f / 16.0f));
    float2 fv = __ldg(fqr2 + tid);

    float2 wf, wa, wm;
    wf = __ldg(W2 + tid);          wa = __ldg(W2 + 256 + tid);  wm = __ldg(W2 + 512 + tid);
    float pv0 = wf.x * fv.x + wf.y * fv.y + wa.x * avg.x + wa.y * avg.y
              + wm.x * mx.x + wm.y * mx.y;
    wf = __ldg(W2 + 768 + tid);    wa = __ldg(W2 + 1024 + tid); wm = __ldg(W2 + 1280 + tid);
    float pv1 = wf.x * fv.x + wf.y * fv.y + wa.x * avg.x + wa.y * avg.y
              + wm.x * mx.x + wm.y * mx.y;
    wf = __ldg(W2 + 1536 + tid);   wa = __ldg(W2 + 1792 + tid); wm = __ldg(W2 + 2048 + tid);
    float pv2 = wf.x * fv.x + wf.y * fv.y + wa.x * avg.x + wa.y * avg.y
              + wm.x * mx.x + wm.y * mx.y;

#pragma unroll
    for (int o = 16; o; o >>= 1) {
        pv0 += __shfl_xor_sync(0xffffffffu, pv0, o);
        pv1 += __shfl_xor_sync(0xffffffffu, pv1, o);
        pv2 += __shfl_xor_sync(0xffffffffu, pv2, o);
    }
    if (lane == 0) { wred[wid] = pv0; wred[8 + wid] = pv1; wred[16 + wid] = pv2; }
    __syncthreads();

    if (tid == 0) {
        float v0 = bvec[0], v1 = bvec[1], v2 = bvec[2];
#pragma unroll
        for (int i = 0; i < 8; i++) { v0 += wred[i]; v1 += wred[8 + i]; v2 += wred[16 + i]; }
        float vin[3] = {v0, v1, v2}, t1[3], t2[3];
        inv3_apply(R1 + (size_t)pt * 9, vin, t1);
        inv3_apply(R2 + (size_t)pt * 9, t1, t2);
        float m = (cen[pt] >= NP) ? 1.0f : 0.0f;
#pragma unroll
        for (int j = 0; j < 3; j++) {
            float qr = q[pt * 3 + j] + t2[j] * m;
            out[49152 + pt * 3 + j] = qr;
            out[98304 + pt * 3 + j] = qr;
        }
    }
}

// ---------------------------------------------------------------------------
// Launch. Inputs: p, q, ffp, ffq, R1, R2, centroids, W, b
// Output: concat(q, q_refine, q_refine, idx) as f32, 409600 elems.
// ---------------------------------------------------------------------------
extern "C" void kernel_launch(void* const* d_in, const int* in_sizes, int n_in,
                              void* d_out, int out_size) {
    const float* q   = (const float*)d_in[1];
    const float* ffp = (const float*)d_in[2];
    const float* ffq = (const float*)d_in[3];
    const float* R1  = (const float*)d_in[4];
    const float* R2  = (const float*)d_in[5];
    const int*   cen = (const int*)d_in[6];
    const float* W   = (const float*)d_in[7];
    const float* bb  = (const float*)d_in[8];
    float* out = (float*)d_out;

    cudaFuncSetAttribute(k_gemm_hmma, cudaFuncAttributeMaxDynamicSharedMemorySize, 65536);

    __half* d_fph; cudaGetSymbolAddress((void**)&d_fph, g_fph);
    __half* d_fqh; cudaGetSymbolAddress((void**)&d_fqh, g_fqh);
    float*  d_gnp; cudaGetSymbolAddress((void**)&d_gnp, g_np);
    float*  d_gnq; cudaGetSymbolAddress((void**)&d_gnq, g_nq);

    cudaMemcpyAsync(out, q, (size_t)NB * NP * 3 * sizeof(float),
                    cudaMemcpyDeviceToDevice);

    dim3 gn(NB * NP / 8, 2);
    k_normalize2<<<gn, 256>>>(ffp, d_fph, d_gnp, ffq, d_fqh, d_gnq);

    dim3 gg(NP / BN, NP / BM, NB);            // (16, 16, 8)
    k_gemm_hmma<<<gg, 256, 65536>>>();

    k_select<<<NB * NP / 4, 128>>>(ffp, ffq, out);

    k_pool<<<NB * NP, 256>>>(ffp, ffq, R1, R2, cen, W, bb, q, out);
}

// round 16
// speedup vs baseline: 1.1367x; 1.1367x over previous
#include <cuda_runtime.h>
#include <cuda_fp16.h>
#include <float.h>
#include <math.h>
#include <stdint.h>

#define NB 8
#define NP 2048
#define ND 512
#define NK 16
#define NCAND 32

// ---------------- device scratch (no allocations allowed) -------------------
__device__ __half g_fqh[(size_t)NB * NP * ND];        // normalized ffq, fp16
__device__ __half g_fph[(size_t)NB * NP * ND];        // normalized ffp, fp16
__device__ float  g_nq[NB * NP];                      // 1/(||ffq||+eps)
__device__ float  g_np[NB * NP];                      // 1/(||ffp||+eps)
__device__ __half g_w1h[(size_t)NB * NP * NP];        // similarity, fp16
__device__ int    g_cand[NB * NP * NCAND];            // top-32 candidates per row
__device__ int    g_sel[NB * NP * NK];                // final top-16 (global idx)

// ---------------- helpers ---------------------------------------------------
__device__ __forceinline__ uint32_t smem_u32(const void* p) {
    uint32_t a;
    asm("{ .reg .u64 t; cvta.to.shared.u64 t, %1; cvt.u32.u64 %0, t; }" : "=r"(a) : "l"(p));
    return a;
}
#define SWZ(off) ((off) ^ (((off) >> 3) & 0x70))

__device__ __forceinline__ void cp16(uint32_t dst, const void* src) {
    asm volatile("cp.async.cg.shared.global [%0], [%1], 16;" :: "r"(dst), "l"(src));
}
#define CP_COMMIT() asm volatile("cp.async.commit_group;" ::: "memory")
#define CP_WAIT(n)  asm volatile("cp.async.wait_group %0;" :: "n"(n) : "memory")

#define LDSM4(r, addr)                                                          \
    asm volatile("ldmatrix.sync.aligned.m8n8.x4.shared.b16 {%0,%1,%2,%3}, [%4];" \
        : "=r"((r)[0]), "=r"((r)[1]), "=r"((r)[2]), "=r"((r)[3]) : "r"(addr))

__device__ __forceinline__ void mma16816(float* d, const uint32_t* a,
                                         uint32_t b0, uint32_t b1) {
    asm volatile(
        "mma.sync.aligned.m16n8k16.row.col.f32.f16.f16.f32 "
        "{%0,%1,%2,%3},{%4,%5,%6,%7},{%8,%9},{%0,%1,%2,%3};"
        : "+f"(d[0]), "+f"(d[1]), "+f"(d[2]), "+f"(d[3])
        : "r"(a[0]), "r"(a[1]), "r"(a[2]), "r"(a[3]), "r"(b0), "r"(b1));
}

// ---------------------------------------------------------------------------
// Normalize rows by (L2 + 1e-8) for both tensors in one launch (blockIdx.y
// selects ffp/ffq). Norm reduction = exact validated R1 arithmetic.
// ---------------------------------------------------------------------------
__global__ void k_normalize2(const float* __restrict__ srcp, __half* __restrict__ dstp,
                             float* __restrict__ invnp,
                             const float* __restrict__ srcq, __half* __restrict__ dstq,
                             float* __restrict__ invnq) {
    const float* src = blockIdx.y ? srcq : srcp;
    __half* dst = blockIdx.y ? dstq : dstp;
    float* invn = blockIdx.y ? invnq : invnp;
    int row  = blockIdx.x * 8 + (threadIdx.x >> 5);
    int lane = threadIdx.x & 31;
    const float* s = src + (size_t)row * ND;
    float ss = 0.f;
    for (int d = lane; d < ND; d += 32) { float v = s[d]; ss = fmaf(v, v, ss); }
#pragma unroll
    for (int o = 16; o; o >>= 1) ss += __shfl_xor_sync(0xffffffffu, ss, o);
    float inv = 1.0f / (sqrtf(ss) + 1e-8f);
    if (lane == 0) invn[row] = inv;
    const float2* s2 = (const float2*)s;
    __half2* d2 = (__half2*)(dst + (size_t)row * ND);
#pragma unroll
    for (int i = 0; i < 8; i++) {
        float2 v = s2[lane + 32 * i];
        d2[lane + 32 * i] = __floats2half2_rn(v.x * inv, v.y * inv);
    }
}

// ---------------------------------------------------------------------------
// HMMA fp16 GEMM: w1[b] = fq[b] @ fp[b]^T -> fp16.
// 128x128 tile, BK=64, cp.async double buffer, 8 warps in 4(M) x 2(N),
// warp tile 32x64, mma.m16n8k16, fp32 accumulate.
// ---------------------------------------------------------------------------
#define BM 128
#define BN 128
#define BK 64

__global__ __launch_bounds__(256) void k_gemm_hmma() {
    extern __shared__ char sm[];
    const uint32_t sb = smem_u32(sm);
    const int tid = threadIdx.x, lane = tid & 31, wid = tid >> 5;
    const int wm = wid & 3, wn = wid >> 2;
    const int bz = blockIdx.z;
    const __half* Ag = g_fqh + ((size_t)bz * NP + blockIdx.y * BM) * ND;
    const __half* Bg = g_fph + ((size_t)bz * NP + blockIdx.x * BN) * ND;

    auto load = [&](int kc, int buf) {
        uint32_t abase = sb + buf * 32768;
        const __half* ap = Ag + kc * BK;
#pragma unroll
        for (int i = 0; i < 4; i++) {
            int id = tid + i * 256;
            int r = id >> 3, c = id & 7;
            cp16(abase + SWZ(r * 128 + c * 16), ap + (size_t)r * ND + c * 8);
        }
        uint32_t bbase = abase + 16384;
        const __half* bp = Bg + kc * BK;
#pragma unroll
        for (int i = 0; i < 4; i++) {
            int id = tid + i * 256;
            int r = id >> 3, c = id & 7;
            cp16(bbase + SWZ(r * 128 + c * 16), bp + (size_t)r * ND + c * 8);
        }
    };

    float acc[2][8][4];
#pragma unroll
    for (int t = 0; t < 2; t++)
#pragma unroll
        for (int n = 0; n < 8; n++)
#pragma unroll
            for (int i = 0; i < 4; i++) acc[t][n][i] = 0.f;

    load(0, 0);
    CP_COMMIT();

    const int lrow = lane & 15;
    const int lk16 = (lane >> 4) * 16;

#pragma unroll 1
    for (int c = 0; c < 8; c++) {
        int buf = c & 1;
        if (c < 7) { load(c + 1, buf ^ 1); CP_COMMIT(); CP_WAIT(1); }
        else       { CP_WAIT(0); }
        __syncthreads();
        uint32_t Asb = sb + buf * 32768;
        uint32_t Bsb = Asb + 16384;
#pragma unroll
        for (int ks = 0; ks < 4; ks++) {
            uint32_t a[2][4];
#pragma unroll
            for (int t = 0; t < 2; t++) {
                int row = wm * 32 + t * 16 + lrow;
                uint32_t off = (uint32_t)(row * 128 + ks * 32 + lk16) ^ ((row & 7) << 4);
                LDSM4(a[t], Asb + off);
            }
            uint32_t bfr[4][4];
#pragma unroll
            for (int j = 0; j < 4; j++) {
                int row = wn * 64 + j * 16 + lrow;
                uint32_t off = (uint32_t)(row * 128 + ks * 32 + lk16) ^ ((row & 7) << 4);
                LDSM4(bfr[j], Bsb + off);
            }
#pragma unroll
            for (int t = 0; t < 2; t++)
#pragma unroll
                for (int n8 = 0; n8 < 8; n8++) {
                    int j = n8 >> 1, hi = n8 & 1;
                    mma16816(acc[t][n8], a[t], bfr[j][hi ? 1 : 0], bfr[j][hi ? 3 : 2]);
                }
        }
        __syncthreads();
    }

    const int q0 = blockIdx.y * BM, p0 = blockIdx.x * BN;
#pragma unroll
    for (int t = 0; t < 2; t++)
#pragma unroll
        for (int n8 = 0; n8 < 8; n8++) {
            int m = q0 + wm * 32 + t * 16 + (lane >> 2);
            int n = p0 + wn * 64 + n8 * 8 + (lane & 3) * 2;
            size_t base = ((size_t)bz * NP + m) * NP + n;
            *(__half2*)(g_w1h + base) =
                __floats2half2_rn(acc[t][n8][0], acc[t][n8][1]);
            *(__half2*)(g_w1h + base + (size_t)8 * NP) =
                __floats2half2_rn(acc[t][n8][2], acc[t][n8][3]);
        }
}

// ---------------------------------------------------------------------------
// Per-row top-32 candidates from fp16 w1. One warp per row; row register-
// resident. Per-lane sorted top-4 buffer; butterfly over lane heads; exact
// rescan fallback on buffer exhaustion. (R13-validated version.)
// ---------------------------------------------------------------------------
__global__ __launch_bounds__(256) void k_cand() {
    int row  = blockIdx.x * 8 + (threadIdx.x >> 5);
    int lane = threadIdx.x & 31;
    const unsigned int* rp = ((const unsigned int*)g_w1h) + (size_t)row * (NP / 2);
    unsigned int rv[32];
#pragma unroll
    for (int i = 0; i < 32; i++) rv[i] = rp[i * 32 + lane];

    float bv0 = -FLT_MAX, bv1 = -FLT_MAX, bv2 = -FLT_MAX, bv3 = -FLT_MAX;
    int   bi0 = 1 << 30,  bi1 = 1 << 30,  bi2 = 1 << 30,  bi3 = 1 << 30;

    auto ins = [&](float v, int id) {
        if (v > bv3) {
            if (v > bv1) {
                if (v > bv0) {
                    bv3 = bv2; bi3 = bi2; bv2 = bv1; bi2 = bi1;
                    bv1 = bv0; bi1 = bi0; bv0 = v;  bi0 = id;
                } else {
                    bv3 = bv2; bi3 = bi2; bv2 = bv1; bi2 = bi1;
                    bv1 = v;  bi1 = id;
                }
            } else {
                if (v > bv2) { bv3 = bv2; bi3 = bi2; bv2 = v; bi2 = id; }
                else         { bv3 = v;  bi3 = id; }
            }
        }
    };
    auto build = [&]() {
        bv0 = bv1 = bv2 = bv3 = -FLT_MAX;
        bi0 = bi1 = bi2 = bi3 = 1 << 30;
#pragma unroll
        for (int i = 0; i < 32; i++) {
            float2 f = __half22float2(*(__half2*)&rv[i]);
            int base = (i * 32 + lane) << 1;
            ins(f.x, base);
            ins(f.y, base + 1);
        }
    };
    build();

    int* outc = g_cand + (size_t)row * NCAND;
#pragma unroll 1
    for (int it = 0; it < NCAND; it++) {
        float wv = bv0; int wi = bi0;
#pragma unroll
        for (int o = 16; o; o >>= 1) {
            float ov = __shfl_xor_sync(0xffffffffu, wv, o);
            int   oi = __shfl_xor_sync(0xffffffffu, wi, o);
            if (ov > wv || (ov == wv && oi < wi)) { wv = ov; wi = oi; }
        }
        if (lane == 0) outc[it] = wi;
        if (bi0 == wi) {
            int slot = wi >> 6;
            __half2 h = *(__half2*)&rv[slot];
            if (wi & 1) h.y = __ushort_as_half((unsigned short)0xFC00);
            else        h.x = __ushort_as_half((unsigned short)0xFC00);
            rv[slot] = *(unsigned int*)&h;
            bv0 = bv1; bi0 = bi1; bv1 = bv2; bi1 = bi2;
            bv2 = bv3; bi2 = bi3; bv3 = -FLT_MAX; bi3 = 1 << 30;
            if (bv0 == -FLT_MAX) build();
        }
    }
}

// ---------------------------------------------------------------------------
// Exact rescore + sort (R13-validated). One WARP per point; cp.async staged,
// XOR-swizzled double-buffered tiles; LDS.128 consumption; fq via registers +
// shfl. Per-candidate mul->fmaf chain over d=0..511 bit-identical to the
// validated kernel. Bitonic sort (desc value, asc index).
// ---------------------------------------------------------------------------
__global__ __launch_bounds__(256) void k_rescore(
    const float* __restrict__ ffp, const float* __restrict__ ffq,
    float* __restrict__ out)
{
    __shared__ __align__(16) float stile[8][2][32 * 32];   // 8 warps x 2 bufs x 4KB
    const int wid = threadIdx.x >> 5, lane = threadIdx.x & 31;
    const int pt = blockIdx.x * 8 + wid;
    const int b = pt >> 11;

    const float* fqr = ffq + (size_t)pt * ND;
    const float invq = g_nq[pt];
    float rqv[16];
#pragma unroll
    for (int i = 0; i < 16; i++) rqv[i] = fqr[i * 32 + lane] * invq;

    const int ci = g_cand[(size_t)pt * NCAND + lane];
    const float invp = g_np[b * NP + ci];
    const float* fpb = ffp + (size_t)b * NP * ND;

    const int part = lane & 7;
    const int rbase = lane >> 3;
    const uint32_t tb0 = smem_u32(stile[wid][0]);
    const uint32_t tb1 = smem_u32(stile[wid][1]);
    const int lsw = lane & 7;

    auto stage = [&](int ch, int buf) {
        uint32_t tb = buf ? tb1 : tb0;
#pragma unroll
        for (int i = 0; i < 8; i++) {
            int r = i * 4 + rbase;
            int cir = __shfl_sync(0xffffffffu, ci, r);
            const float* src = fpb + (size_t)cir * ND + ch * 32 + part * 4;
            uint32_t dst = tb + (uint32_t)(r * 128 + ((part ^ (r & 7)) << 4));
            cp16(dst, src);
        }
    };

    stage(0, 0);
    CP_COMMIT();

    float acc = 0.f;
#pragma unroll
    for (int ch = 0; ch < 16; ch++) {
        const int buf = ch & 1;
        if (ch < 15) { stage(ch + 1, buf ^ 1); CP_COMMIT(); CP_WAIT(1); }
        else         { CP_WAIT(0); }
        __syncwarp();
        const float* tb = (const float*)(buf ? stile[wid][1] : stile[wid][0]) + lane * 32;
#pragma unroll
        for (int j = 0; j < 8; j++) {
            float4 v = *(const float4*)(tb + ((j ^ lsw) << 2));
            float s0 = __shfl_sync(0xffffffffu, rqv[ch], j * 4 + 0);
            float s1 = __shfl_sync(0xffffffffu, rqv[ch], j * 4 + 1);
            float s2 = __shfl_sync(0xffffffffu, rqv[ch], j * 4 + 2);
            float s3 = __shfl_sync(0xffffffffu, rqv[ch], j * 4 + 3);
            acc = fmaf(v.x * invp, s0, acc);     // strictly sequential, fused
            acc = fmaf(v.y * invp, s1, acc);
            acc = fmaf(v.z * invp, s2, acc);
            acc = fmaf(v.w * invp, s3, acc);
        }
        __syncwarp();
    }

    unsigned int u = __float_as_uint(acc);
    unsigned int ou = (u & 0x80000000u) ? ~u : (u | 0x80000000u);
    unsigned long long key =
        ((unsigned long long)(~ou) << 32) | (unsigned)((ci << 5) | lane);
#pragma unroll
    for (int k = 2; k <= 32; k <<= 1) {
#pragma unroll
        for (int j = k >> 1; j > 0; j >>= 1) {
            unsigned long long o = __shfl_xor_sync(0xffffffffu, key, j);
            bool dirUp = ((lane & k) == 0);
            bool lower = ((lane & j) == 0);
            unsigned long long mn = (key < o) ? key : o;
            unsigned long long mx = (key < o) ? o : key;
            key = (lower == dirUp) ? mn : mx;
        }
    }
    if (lane < NK) {
        int idx = (int)((key >> 5) & 2047u);
        g_sel[pt * NK + lane] = idx;
        out[3 * NB * NP * 3 + pt * NK + lane] = (float)idx;
    }
}

// ---------------------------------------------------------------------------
// 3x3 inverse (adjugate) applied to a vector.
// ---------------------------------------------------------------------------
__device__ __forceinline__ void inv3_apply(const float* __restrict__ M,
                                           const float* __restrict__ v,
                                           float* __restrict__ o) {
    float a = M[0], b = M[1], c = M[2];
    float d = M[3], e = M[4], f = M[5];
    float g = M[6], h = M[7], i = M[8];
    float A  = e * i - f * h;
    float Bc = -(d * i - f * g);
    float Cc = d * h - e * g;
    float det = a * A + b * Bc + c * Cc;
    float id = 1.0f / det;
    float i00 = A * id,  i01 = -(b * i - c * h) * id, i02 = (b * f - c * e) * id;
    float i10 = Bc * id, i11 = (a * i - c * g) * id,  i12 = -(a * f - c * d) * id;
    float i20 = Cc * id, i21 = -(a * h - b * g) * id, i22 = (a * e - b * d) * id;
    o[0] = i00 * v[0] + i01 * v[1] + i02 * v[2];
    o[1] = i10 * v[0] + i11 * v[1] + i12 * v[2];
    o[2] = i20 * v[0] + i21 * v[1] + i22 * v[2];
}

// ---------------------------------------------------------------------------
// Pool (avg/max over the 16 winners) + refine linear + rotate-back + mask +
// add q. One 128-thread block per point; float4 loads: each thread owns 4
// adjacent channels (16 LDG.128 + 9 W float4 + 1 fq float4). Per-channel
// pooling math identical; only reduction grouping changes (~1e-9 effect).
// ---------------------------------------------------------------------------
__global__ __launch_bounds__(128) void k_pool(
    const float* __restrict__ ffp, const float* __restrict__ ffq,
    const float* __restrict__ R1,  const float* __restrict__ R2,
    const int*   __restrict__ cen, const float* __restrict__ W,
    const float* __restrict__ bvec, const float* __restrict__ q,
    float* __restrict__ out)
{
    __shared__ int   ssel[NK];
    __shared__ float wred[12];
    const int pt = blockIdx.x, b = pt >> 11;
    const int tid = threadIdx.x, lane = tid & 31, wid = tid >> 5;

    if (tid < NK) ssel[tid] = g_sel[pt * NK + tid];
    __syncthreads();

    const float* fpb = ffp + (size_t)b * NP * ND;
    const float4* fqr4 = (const float4*)(ffq + (size_t)pt * ND);
    const float4* W4 = (const float4*)W;

    float4 s = make_float4(0.f, 0.f, 0.f, 0.f);
    float4 mx = make_float4(-FLT_MAX, -FLT_MAX, -FLT_MAX, -FLT_MAX);
#pragma unroll
    for (int k = 0; k < NK; k++) {
        float4 v = __ldg((const float4*)(fpb + (size_t)ssel[k] * ND) + tid);
        s.x += v.x; s.y += v.y; s.z += v.z; s.w += v.w;
        mx.x = fmaxf(mx.x, v.x); mx.y = fmaxf(mx.y, v.y);
        mx.z = fmaxf(mx.z, v.z); mx.w = fmaxf(mx.w, v.w);
    }
    const float r16 = 1.0f / 16.0f;
    float4 avg = make_float4(s.x * r16, s.y * r16, s.z * r16, s.w * r16);
    float4 fv = __ldg(fqr4 + tid);

    float pv[3];
#pragma unroll
    for (int r = 0; r < 3; r++) {
        float4 wf = __ldg(W4 + r * 384 + tid);
        float4 wa = __ldg(W4 + r * 384 + 128 + tid);
        float4 wm = __ldg(W4 + r * 384 + 256 + tid);
        pv[r] = wf.x * fv.x + wf.y * fv.y + wf.z * fv.z + wf.w * fv.w
              + wa.x * avg.x + wa.y * avg.y + wa.z * avg.z + wa.w * avg.w
              + wm.x * mx.x + wm.y * mx.y + wm.z * mx.z + wm.w * mx.w;
    }
#pragma unroll
    for (int r = 0; r < 3; r++)
#pragma unroll
        for (int o = 16; o; o >>= 1)
            pv[r] += __shfl_xor_sync(0xffffffffu, pv[r], o);
    if (lane == 0) { wred[wid] = pv[0]; wred[4 + wid] = pv[1]; wred[8 + wid] = pv[2]; }
    __syncthreads();

    if (tid == 0) {
        float v0 = bvec[0], v1 = bvec[1], v2 = bvec[2];
#pragma unroll
        for (int i = 0; i < 4; i++) { v0 += wred[i]; v1 += wred[4 + i]; v2 += wred[8 + i]; }
        float vin[3] = {v0, v1, v2}, t1[3], t2[3];
        inv3_apply(R1 + (size_t)pt * 9, vin, t1);
        inv3_apply(R2 + (size_t)pt * 9, t1, t2);
        float m = (cen[pt] >= NP) ? 1.0f : 0.0f;
#pragma unroll
        for (int j = 0; j < 3; j++) {
            float qr = q[pt * 3 + j] + t2[j] * m;
            out[49152 + pt * 3 + j] = qr;
            out[98304 + pt * 3 + j] = qr;
        }
    }
}

// ---------------------------------------------------------------------------
// Launch. Inputs: p, q, ffp, ffq, R1, R2, centroids, W, b
// Output: concat(q, q_refine, q_refine, idx) as f32, 409600 elems.
// ---------------------------------------------------------------------------
extern "C" void kernel_launch(void* const* d_in, const int* in_sizes, int n_in,
                              void* d_out, int out_size) {
    const float* q   = (const float*)d_in[1];
    const float* ffp = (const float*)d_in[2];
    const float* ffq = (const float*)d_in[3];
    const float* R1  = (const float*)d_in[4];
    const float* R2  = (const float*)d_in[5];
    const int*   cen = (const int*)d_in[6];
    const float* W   = (const float*)d_in[7];
    const float* bb  = (const float*)d_in[8];
    float* out = (float*)d_out;

    cudaFuncSetAttribute(k_gemm_hmma, cudaFuncAttributeMaxDynamicSharedMemorySize, 65536);

    __half* d_fph; cudaGetSymbolAddress((void**)&d_fph, g_fph);
    __half* d_fqh; cudaGetSymbolAddress((void**)&d_fqh, g_fqh);
    float*  d_gnp; cudaGetSymbolAddress((void**)&d_gnp, g_np);
    float*  d_gnq; cudaGetSymbolAddress((void**)&d_gnq, g_nq);

    cudaMemcpyAsync(out, q, (size_t)NB * NP * 3 * sizeof(float),
                    cudaMemcpyDeviceToDevice);

    dim3 gn(NB * NP / 8, 2);
    k_normalize2<<<gn, 256>>>(ffp, d_fph, d_gnp, ffq, d_fqh, d_gnq);

    dim3 gg(NP / BN, NP / BM, NB);            // (16, 16, 8)
    k_gemm_hmma<<<gg, 256, 65536>>>();

    k_cand<<<NB * NP / 8, 256>>>();

    k_rescore<<<NB * NP / 8, 256>>>(ffp, ffq, out);

    k_pool<<<NB * NP, 128>>>(ffp, ffq, R1, R2, cen, W, bb, q, out);
}